// round 1
// baseline (speedup 1.0000x reference)
#include <cuda_runtime.h>
#include <math.h>

#define LQ   40000
#define DMOD 256
#define NH   8
#define NP   4
#define DH   32
#define HSP  200
#define WSP  200

// ---------------- scratch (no allocations allowed) ----------------
__device__ float g_q[LQ * DMOD];        // query + query_pos
__device__ float g_value[LQ * DMOD];    // value projection
__device__ float g_off[LQ * NH * NP * 2];
__device__ float g_attn[LQ * NH * NP];  // attention logits (softmax in sampler)
__device__ float g_sampled[LQ * DMOD];

// ---------------- elementwise add (float4) ----------------
__global__ void add_kernel(const float4* __restrict__ a,
                           const float4* __restrict__ b,
                           float4* __restrict__ c, int n4) {
    int i = blockIdx.x * blockDim.x + threadIdx.x;
    if (i < n4) {
        float4 va = a[i], vb = b[i];
        va.x += vb.x; va.y += vb.y; va.z += vb.z; va.w += vb.w;
        c[i] = va;
    }
}

// ---------------- SGEMM: C[M,N] = A[M,K] @ B[N,K]^T + bias[N] ----------------
// Row-major A, row-major B (i.e. NT gemm). K, N multiples of BK/BN; M guarded.
template <int BM, int BN, int BK, int TM, int TN>
__global__ __launch_bounds__((BM / TM) * (BN / TN))
void sgemm_nt(const float* __restrict__ A, const float* __restrict__ Bw,
              const float* __restrict__ bias, float* __restrict__ C,
              int M, int N, int K) {
    constexpr int TX = BN / TN;
    constexpr int TY = BM / TM;
    constexpr int NT = TX * TY;

    __shared__ float As[BK][BM];
    __shared__ float Bs[BK][BN];

    const int tid = threadIdx.x;
    const int bm = blockIdx.y * BM;
    const int bn = blockIdx.x * BN;
    const int tx = tid % TX;
    const int ty = tid / TX;

    float acc[TM][TN];
#pragma unroll
    for (int i = 0; i < TM; i++)
#pragma unroll
        for (int j = 0; j < TN; j++) acc[i][j] = 0.0f;

    for (int k0 = 0; k0 < K; k0 += BK) {
        // Load A tile: BM rows x BK cols as float4
#pragma unroll
        for (int i = tid; i < BM * (BK / 4); i += NT) {
            int m = i / (BK / 4);
            int s = (i % (BK / 4)) * 4;
            int row = bm + m;
            row = row < M ? row : M - 1;  // clamp; garbage rows never stored
            float4 v = *reinterpret_cast<const float4*>(A + (size_t)row * K + k0 + s);
            As[s + 0][m] = v.x; As[s + 1][m] = v.y;
            As[s + 2][m] = v.z; As[s + 3][m] = v.w;
        }
        // Load B tile: BN rows x BK cols as float4 (N is always tile-aligned)
#pragma unroll
        for (int i = tid; i < BN * (BK / 4); i += NT) {
            int n = i / (BK / 4);
            int s = (i % (BK / 4)) * 4;
            float4 v = *reinterpret_cast<const float4*>(Bw + (size_t)(bn + n) * K + k0 + s);
            Bs[s + 0][n] = v.x; Bs[s + 1][n] = v.y;
            Bs[s + 2][n] = v.z; Bs[s + 3][n] = v.w;
        }
        __syncthreads();

#pragma unroll
        for (int kk = 0; kk < BK; kk++) {
            float a[TM], b[TN];
#pragma unroll
            for (int i = 0; i < TM; i++) a[i] = As[kk][ty + i * TY];
#pragma unroll
            for (int j = 0; j < TN; j++) b[j] = Bs[kk][tx + j * TX];
#pragma unroll
            for (int i = 0; i < TM; i++)
#pragma unroll
                for (int j = 0; j < TN; j++)
                    acc[i][j] = fmaf(a[i], b[j], acc[i][j]);
        }
        __syncthreads();
    }

#pragma unroll
    for (int i = 0; i < TM; i++) {
        int row = bm + ty + i * TY;
        if (row < M) {
#pragma unroll
            for (int j = 0; j < TN; j++) {
                int col = bn + tx + j * TX;
                C[(size_t)row * N + col] = acc[i][j] + bias[col];
            }
        }
    }
}

// ---------------- fused softmax + bilinear sampling + P-sum ----------------
// grid = LQ blocks, 256 threads: warp w = head w, lane = channel d (DH=32)
__global__ __launch_bounds__(NH * 32)
void sample_kernel(const float* __restrict__ refpts) {
    const int q = blockIdx.x;
    const int h = threadIdx.x >> 5;
    const int lane = threadIdx.x & 31;

    const float refx = refpts[q * 2 + 0];
    const float refy = refpts[q * 2 + 1];

    // softmax over the 4 points (redundant per lane; broadcast loads)
    float lg[NP];
#pragma unroll
    for (int p = 0; p < NP; p++) lg[p] = g_attn[q * (NH * NP) + h * NP + p];
    float mx = fmaxf(fmaxf(lg[0], lg[1]), fmaxf(lg[2], lg[3]));
    float e[NP], esum = 0.0f;
#pragma unroll
    for (int p = 0; p < NP; p++) { e[p] = expf(lg[p] - mx); esum += e[p]; }
    const float inv = 1.0f / esum;

    const float* __restrict__ vbase = g_value + h * DH + lane;

    float acc = 0.0f;
#pragma unroll
    for (int p = 0; p < NP; p++) {
        const float ap = e[p] * inv;
        const float ox = g_off[q * (NH * NP * 2) + h * (NP * 2) + p * 2 + 0];
        const float oy = g_off[q * (NH * NP * 2) + h * (NP * 2) + p * 2 + 1];
        // match reference exactly: loc = ref + off/norm; x = loc*W - 0.5
        const float x = (refx + ox * (1.0f / WSP)) * WSP - 0.5f;
        const float y = (refy + oy * (1.0f / HSP)) * HSP - 0.5f;

        const float x0f = floorf(x), y0f = floorf(y);
        const int x0 = (int)x0f, y0 = (int)y0f;
        const float lw = x - x0f, lh = y - y0f;

        const float w00 = (1.0f - lh) * (1.0f - lw);
        const float w01 = (1.0f - lh) * lw;
        const float w10 = lh * (1.0f - lw);
        const float w11 = lh * lw;

        const int x1 = x0 + 1, y1 = y0 + 1;
        const bool vx0 = (x0 >= 0) & (x0 < WSP);
        const bool vx1 = (x1 >= 0) & (x1 < WSP);
        const bool vy0 = (y0 >= 0) & (y0 < HSP);
        const bool vy1 = (y1 >= 0) & (y1 < HSP);

        if (vy0 & vx0) acc += ap * w00 * vbase[(size_t)(y0 * WSP + x0) * DMOD];
        if (vy0 & vx1) acc += ap * w01 * vbase[(size_t)(y0 * WSP + x1) * DMOD];
        if (vy1 & vx0) acc += ap * w10 * vbase[(size_t)(y1 * WSP + x0) * DMOD];
        if (vy1 & vx1) acc += ap * w11 * vbase[(size_t)(y1 * WSP + x1) * DMOD];
    }
    g_sampled[(size_t)q * DMOD + h * DH + lane] = acc;
}

// ---------------- launch ----------------
extern "C" void kernel_launch(void* const* d_in, const int* in_sizes, int n_in,
                              void* d_out, int out_size) {
    const float* query  = (const float*)d_in[0];
    const float* qpos   = (const float*)d_in[1];
    const float* refpts = (const float*)d_in[2];
    const float* inp    = (const float*)d_in[3];
    const float* Wv     = (const float*)d_in[4];
    const float* bv     = (const float*)d_in[5];
    const float* Woff   = (const float*)d_in[6];
    const float* boff   = (const float*)d_in[7];
    const float* Wattn  = (const float*)d_in[8];
    const float* battn  = (const float*)d_in[9];
    const float* Wout   = (const float*)d_in[10];
    const float* bout   = (const float*)d_in[11];
    float* out = (float*)d_out;

    float *p_q, *p_val, *p_off, *p_attn, *p_samp;
    cudaGetSymbolAddress((void**)&p_q, g_q);
    cudaGetSymbolAddress((void**)&p_val, g_value);
    cudaGetSymbolAddress((void**)&p_off, g_off);
    cudaGetSymbolAddress((void**)&p_attn, g_attn);
    cudaGetSymbolAddress((void**)&p_samp, g_sampled);

    const int M = LQ, K = DMOD;

    // 1. q = query + query_pos
    {
        int n4 = (LQ * DMOD) / 4;
        add_kernel<<<(n4 + 255) / 256, 256>>>(
            (const float4*)query, (const float4*)qpos, (float4*)p_q, n4);
    }

    const int gy = (M + 127) / 128;

    // 2. value = input_flatten @ W_value^T + b_value   (40000x256x256)
    sgemm_nt<128, 128, 16, 8, 8><<<dim3(DMOD / 128, gy), 256>>>(
        inp, Wv, bv, p_val, M, DMOD, K);

    // 3. off = q @ W_off^T + b_off   (N=64)
    sgemm_nt<128, 64, 16, 8, 4><<<dim3(1, gy), 256>>>(
        p_q, Woff, boff, p_off, M, 64, K);

    // 4. attn logits = q @ W_attn^T + b_attn   (N=32)
    sgemm_nt<128, 32, 16, 8, 2><<<dim3(1, gy), 256>>>(
        p_q, Wattn, battn, p_attn, M, 32, K);

    // 5. fused softmax + bilinear sampling
    sample_kernel<<<LQ, NH * 32>>>(refpts);

    // 6. out = sampled @ W_out^T + b_out
    sgemm_nt<128, 128, 16, 8, 8><<<dim3(DMOD / 128, gy), 256>>>(
        p_samp, Wout, bout, out, M, DMOD, K);
}

// round 3
// speedup vs baseline: 2.9181x; 2.9181x over previous
#include <cuda_runtime.h>
#include <cstdint>
#include <math.h>

#define LQ   40000
#define DMOD 256
#define NH   8
#define NP   4
#define DH   32
#define HSP  200
#define WSP  200

// ---------------- scratch (no allocations allowed) ----------------
__device__ float g_value[LQ * DMOD];
__device__ float g_off[LQ * NH * NP * 2];
__device__ float g_attn[LQ * NH * NP];
__device__ float g_sampled[LQ * DMOD];

// ---------------- helpers ----------------
__device__ __forceinline__ uint32_t tf32_rna(float x) {
    uint32_t u;
    asm("cvt.rna.tf32.f32 %0, %1;" : "=r"(u) : "f"(x));
    return u;
}
__device__ __forceinline__ void mma16n8k8(float* c, const uint32_t* a, const uint32_t* b) {
    asm volatile(
        "mma.sync.aligned.m16n8k8.row.col.f32.tf32.tf32.f32 "
        "{%0,%1,%2,%3}, {%4,%5,%6,%7}, {%8,%9}, {%0,%1,%2,%3};"
        : "+f"(c[0]), "+f"(c[1]), "+f"(c[2]), "+f"(c[3])
        : "r"(a[0]), "r"(a[1]), "r"(a[2]), "r"(a[3]), "r"(b[0]), "r"(b[1]));
}

// ---------------- tf32 tensor-core GEMM: C[M,N] = A[M,K=256] @ B[N,K]^T + bias ----------------
// A (optionally +A2) row-major, B row-major (NT). BM=128, BK=32, warp tile 64x32.
template<int BN>
__global__ __launch_bounds__(2 * (BN / 32) * 32)
void mma_gemm(const float* __restrict__ A, const float* __restrict__ A2,
              const float* __restrict__ Bw, const float* __restrict__ bias,
              float* __restrict__ C, int M, int N) {
    constexpr int BM = 128;
    constexpr int BK = 32;
    constexpr int LD = 36;                 // padded stride: STS.128 + frag LDS conflict-free
    constexpr int NW = 2 * (BN / 32);
    constexpr int NT = NW * 32;

    __shared__ float As[BM * LD];
    __shared__ float Bs[BN * LD];

    const int tid = threadIdx.x;
    const int wid = tid >> 5;
    const int lane = tid & 31;
    const int wm = wid & 1;                // warp row (0..1): 64 rows each
    const int wn = wid >> 1;               // warp col (0..BN/32-1): 32 cols each
    const int bm = blockIdx.y * BM;
    const int bn = blockIdx.x * BN;

    const int lq = lane >> 2;              // lane/4: 0..7
    const int lr = lane & 3;               // lane%4: 0..3

    float acc[4][4][4];
#pragma unroll
    for (int i = 0; i < 4; i++)
#pragma unroll
        for (int j = 0; j < 4; j++)
#pragma unroll
            for (int r = 0; r < 4; r++) acc[i][j][r] = 0.0f;

    for (int k0 = 0; k0 < DMOD; k0 += BK) {
        // ---- load A tile: 128 rows x 32 floats (8 float4/row) ----
#pragma unroll
        for (int idx = tid; idx < BM * 8; idx += NT) {
            int row = idx >> 3, f = idx & 7;
            int gr = bm + row; gr = gr < M ? gr : M - 1;
            float4 v = *reinterpret_cast<const float4*>(A + (size_t)gr * DMOD + k0 + f * 4);
            if (A2) {
                float4 w = *reinterpret_cast<const float4*>(A2 + (size_t)gr * DMOD + k0 + f * 4);
                v.x += w.x; v.y += w.y; v.z += w.z; v.w += w.w;
            }
            uint4 t = make_uint4(tf32_rna(v.x), tf32_rna(v.y), tf32_rna(v.z), tf32_rna(v.w));
            *reinterpret_cast<uint4*>(&As[row * LD + f * 4]) = t;
        }
        // ---- load B tile: BN rows x 32 floats ----
#pragma unroll
        for (int idx = tid; idx < BN * 8; idx += NT) {
            int row = idx >> 3, f = idx & 7;
            float4 v = *reinterpret_cast<const float4*>(Bw + (size_t)(bn + row) * DMOD + k0 + f * 4);
            uint4 t = make_uint4(tf32_rna(v.x), tf32_rna(v.y), tf32_rna(v.z), tf32_rna(v.w));
            *reinterpret_cast<uint4*>(&Bs[row * LD + f * 4]) = t;
        }
        __syncthreads();

        // ---- compute: 4 k-steps of 8 ----
#pragma unroll
        for (int ks = 0; ks < 4; ks++) {
            const int kk = ks * 8;
            uint32_t a[4][4], b[4][2];
#pragma unroll
            for (int mi = 0; mi < 4; mi++) {
                const float* p = &As[(wm * 64 + mi * 16 + lq) * LD + kk + lr];
                a[mi][0] = __float_as_uint(p[0]);
                a[mi][1] = __float_as_uint(p[8 * LD]);
                a[mi][2] = __float_as_uint(p[4]);
                a[mi][3] = __float_as_uint(p[8 * LD + 4]);
            }
#pragma unroll
            for (int ni = 0; ni < 4; ni++) {
                const float* p = &Bs[(wn * 32 + ni * 8 + lq) * LD + kk + lr];
                b[ni][0] = __float_as_uint(p[0]);
                b[ni][1] = __float_as_uint(p[4]);
            }
#pragma unroll
            for (int mi = 0; mi < 4; mi++)
#pragma unroll
                for (int ni = 0; ni < 4; ni++)
                    mma16n8k8(acc[mi][ni], a[mi], b[ni]);
        }
        __syncthreads();
    }

    // ---- epilogue: add bias, store (float2 per fragment half) ----
#pragma unroll
    for (int mi = 0; mi < 4; mi++) {
        const int row0 = bm + wm * 64 + mi * 16 + lq;
#pragma unroll
        for (int ni = 0; ni < 4; ni++) {
            const int col = bn + wn * 32 + ni * 8 + lr * 2;
            const float bz0 = bias[col], bz1 = bias[col + 1];
            if (row0 < M) {
                float2 o = make_float2(acc[mi][ni][0] + bz0, acc[mi][ni][1] + bz1);
                *reinterpret_cast<float2*>(C + (size_t)row0 * N + col) = o;
            }
            if (row0 + 8 < M) {
                float2 o = make_float2(acc[mi][ni][2] + bz0, acc[mi][ni][3] + bz1);
                *reinterpret_cast<float2*>(C + (size_t)(row0 + 8) * N + col) = o;
            }
        }
    }
}

// ---------------- fused softmax + bilinear sampling + P-sum ----------------
__global__ __launch_bounds__(NH * 32)
void sample_kernel(const float* __restrict__ refpts) {
    const int q = blockIdx.x;
    const int h = threadIdx.x >> 5;
    const int lane = threadIdx.x & 31;

    const float refx = refpts[q * 2 + 0];
    const float refy = refpts[q * 2 + 1];

    float lg[NP];
#pragma unroll
    for (int p = 0; p < NP; p++) lg[p] = g_attn[q * (NH * NP) + h * NP + p];
    float mx = fmaxf(fmaxf(lg[0], lg[1]), fmaxf(lg[2], lg[3]));
    float e[NP], esum = 0.0f;
#pragma unroll
    for (int p = 0; p < NP; p++) { e[p] = expf(lg[p] - mx); esum += e[p]; }
    const float inv = 1.0f / esum;

    const float* __restrict__ vbase = g_value + h * DH + lane;

    float acc = 0.0f;
#pragma unroll
    for (int p = 0; p < NP; p++) {
        const float ap = e[p] * inv;
        const float ox = g_off[q * (NH * NP * 2) + h * (NP * 2) + p * 2 + 0];
        const float oy = g_off[q * (NH * NP * 2) + h * (NP * 2) + p * 2 + 1];
        const float x = (refx + ox * (1.0f / WSP)) * WSP - 0.5f;
        const float y = (refy + oy * (1.0f / HSP)) * HSP - 0.5f;

        const float x0f = floorf(x), y0f = floorf(y);
        const int x0 = (int)x0f, y0 = (int)y0f;
        const float lw = x - x0f, lh = y - y0f;

        const float w00 = (1.0f - lh) * (1.0f - lw);
        const float w01 = (1.0f - lh) * lw;
        const float w10 = lh * (1.0f - lw);
        const float w11 = lh * lw;

        const int x1 = x0 + 1, y1 = y0 + 1;
        const bool vx0 = (x0 >= 0) & (x0 < WSP);
        const bool vx1 = (x1 >= 0) & (x1 < WSP);
        const bool vy0 = (y0 >= 0) & (y0 < HSP);
        const bool vy1 = (y1 >= 0) & (y1 < HSP);

        if (vy0 & vx0) acc += ap * w00 * vbase[(size_t)(y0 * WSP + x0) * DMOD];
        if (vy0 & vx1) acc += ap * w01 * vbase[(size_t)(y0 * WSP + x1) * DMOD];
        if (vy1 & vx0) acc += ap * w10 * vbase[(size_t)(y1 * WSP + x0) * DMOD];
        if (vy1 & vx1) acc += ap * w11 * vbase[(size_t)(y1 * WSP + x1) * DMOD];
    }
    g_sampled[(size_t)q * DMOD + h * DH + lane] = acc;
}

// ---------------- launch ----------------
extern "C" void kernel_launch(void* const* d_in, const int* in_sizes, int n_in,
                              void* d_out, int out_size) {
    const float* query  = (const float*)d_in[0];
    const float* qpos   = (const float*)d_in[1];
    const float* refpts = (const float*)d_in[2];
    const float* inp    = (const float*)d_in[3];
    const float* Wv     = (const float*)d_in[4];
    const float* bv     = (const float*)d_in[5];
    const float* Woff   = (const float*)d_in[6];
    const float* boff   = (const float*)d_in[7];
    const float* Wattn  = (const float*)d_in[8];
    const float* battn  = (const float*)d_in[9];
    const float* Wout   = (const float*)d_in[10];
    const float* bout   = (const float*)d_in[11];
    float* out = (float*)d_out;

    float *p_val, *p_off, *p_attn, *p_samp;
    cudaGetSymbolAddress((void**)&p_val, g_value);
    cudaGetSymbolAddress((void**)&p_off, g_off);
    cudaGetSymbolAddress((void**)&p_attn, g_attn);
    cudaGetSymbolAddress((void**)&p_samp, g_sampled);

    const int gy = (LQ + 127) / 128;  // 313

    // 1. value = input_flatten @ W_value^T + b_value
    mma_gemm<128><<<dim3(2, gy), 256>>>(inp, nullptr, Wv, bv, p_val, LQ, DMOD);

    // 2. off = (query+query_pos) @ W_off^T + b_off  (add fused into A loader)
    mma_gemm<64><<<dim3(1, gy), 128>>>(query, qpos, Woff, boff, p_off, LQ, 64);

    // 3. attn logits = (query+query_pos) @ W_attn^T + b_attn
    mma_gemm<32><<<dim3(1, gy), 64>>>(query, qpos, Wattn, battn, p_attn, LQ, 32);

    // 4. fused softmax + bilinear sampling
    sample_kernel<<<LQ, NH * 32>>>(refpts);

    // 5. out = sampled @ W_out^T + b_out
    mma_gemm<128><<<dim3(2, gy), 256>>>(p_samp, Wout == nullptr ? nullptr : nullptr, Wout, bout, out, LQ, DMOD);
}

// round 4
// speedup vs baseline: 4.2444x; 1.4545x over previous
#include <cuda_runtime.h>
#include <cstdint>
#include <math.h>

#define LQ   40000
#define DMOD 256
#define NH   8
#define NP   4
#define DH   32
#define HSP  200
#define WSP  200
#define GQ   8      // queries per sampler block

// ---------------- scratch (no allocations allowed) ----------------
__device__ float g_value[LQ * DMOD];
__device__ float g_oa[LQ * 96];       // combined [off(64) | attn(32)] per query
__device__ float g_sampled[LQ * DMOD];

// ---------------- helpers ----------------
__device__ __forceinline__ uint32_t tf32_rna(float x) {
    uint32_t u;
    asm("cvt.rna.tf32.f32 %0, %1;" : "=r"(u) : "f"(x));
    return u;
}
__device__ __forceinline__ void mma16n8k8(float* c, const uint32_t* a, const uint32_t* b) {
    asm volatile(
        "mma.sync.aligned.m16n8k8.row.col.f32.tf32.tf32.f32 "
        "{%0,%1,%2,%3}, {%4,%5,%6,%7}, {%8,%9}, {%0,%1,%2,%3};"
        : "+f"(c[0]), "+f"(c[1]), "+f"(c[2]), "+f"(c[3])
        : "r"(a[0]), "r"(a[1]), "r"(a[2]), "r"(a[3]), "r"(b[0]), "r"(b[1]));
}

// ---------------- tf32 tensor-core GEMM: C[M,N] = A[M,256] @ B[N,256]^T + bias ----------------
// SPLIT: B rows [0,64) from B1, [64,BN) from B2 (same for bias). Register-prefetch pipeline.
template<int BN, bool SPLIT>
__global__ __launch_bounds__(2 * (BN / 32) * 32, 1)
void mma_gemm(const float* __restrict__ A, const float* __restrict__ A2,
              const float* __restrict__ B1, const float* __restrict__ B2,
              const float* __restrict__ bias1, const float* __restrict__ bias2,
              float* __restrict__ C, int M, int N) {
    constexpr int BM = 128;
    constexpr int BK = 32;
    constexpr int LD = 36;
    constexpr int NW = 2 * (BN / 32);
    constexpr int NT = NW * 32;
    constexpr int AITER = (BM * 8 + NT - 1) / NT;
    constexpr int BITER = (BN * 8 + NT - 1) / NT;

    __shared__ float As[BM * LD];
    __shared__ float Bs[BN * LD];

    const int tid = threadIdx.x;
    const int wid = tid >> 5;
    const int lane = tid & 31;
    const int wm = wid & 1;
    const int wn = wid >> 1;
    const int bm = blockIdx.y * BM;
    const int bn = blockIdx.x * BN;
    const int lq = lane >> 2;
    const int lr = lane & 3;

    float acc[4][4][4];
#pragma unroll
    for (int i = 0; i < 4; i++)
#pragma unroll
        for (int j = 0; j < 4; j++)
#pragma unroll
            for (int r = 0; r < 4; r++) acc[i][j][r] = 0.0f;

    float4 ra[AITER], rb[BITER];

    auto load_tiles = [&](int k0) {
#pragma unroll
        for (int i = 0; i < AITER; i++) {
            int idx = tid + i * NT;
            if (AITER * NT == BM * 8 || idx < BM * 8) {
                int row = idx >> 3, f = idx & 7;
                int gr = bm + row; gr = gr < M ? gr : M - 1;
                float4 v = *reinterpret_cast<const float4*>(A + (size_t)gr * DMOD + k0 + f * 4);
                if (A2) {
                    float4 w = *reinterpret_cast<const float4*>(A2 + (size_t)gr * DMOD + k0 + f * 4);
                    v.x += w.x; v.y += w.y; v.z += w.z; v.w += w.w;
                }
                ra[i] = v;
            }
        }
#pragma unroll
        for (int i = 0; i < BITER; i++) {
            int idx = tid + i * NT;
            if (BITER * NT == BN * 8 || idx < BN * 8) {
                int row = idx >> 3, f = idx & 7;
                const float* bp;
                if (SPLIT)
                    bp = (bn + row) < 64 ? B1 + (size_t)(bn + row) * DMOD
                                         : B2 + (size_t)(bn + row - 64) * DMOD;
                else
                    bp = B1 + (size_t)(bn + row) * DMOD;
                rb[i] = *reinterpret_cast<const float4*>(bp + k0 + f * 4);
            }
        }
    };

    auto store_smem = [&]() {
#pragma unroll
        for (int i = 0; i < AITER; i++) {
            int idx = tid + i * NT;
            if (AITER * NT == BM * 8 || idx < BM * 8) {
                int row = idx >> 3, f = idx & 7;
                uint4 t = make_uint4(tf32_rna(ra[i].x), tf32_rna(ra[i].y),
                                     tf32_rna(ra[i].z), tf32_rna(ra[i].w));
                *reinterpret_cast<uint4*>(&As[row * LD + f * 4]) = t;
            }
        }
#pragma unroll
        for (int i = 0; i < BITER; i++) {
            int idx = tid + i * NT;
            if (BITER * NT == BN * 8 || idx < BN * 8) {
                int row = idx >> 3, f = idx & 7;
                uint4 t = make_uint4(tf32_rna(rb[i].x), tf32_rna(rb[i].y),
                                     tf32_rna(rb[i].z), tf32_rna(rb[i].w));
                *reinterpret_cast<uint4*>(&Bs[row * LD + f * 4]) = t;
            }
        }
    };

    load_tiles(0);

    for (int c = 0; c < DMOD / BK; c++) {
        store_smem();
        __syncthreads();
        if (c < DMOD / BK - 1) load_tiles((c + 1) * BK);

#pragma unroll
        for (int ks = 0; ks < 4; ks++) {
            const int kk = ks * 8;
            uint32_t a[4][4], b[4][2];
#pragma unroll
            for (int mi = 0; mi < 4; mi++) {
                const float* p = &As[(wm * 64 + mi * 16 + lq) * LD + kk + lr];
                a[mi][0] = __float_as_uint(p[0]);
                a[mi][1] = __float_as_uint(p[8 * LD]);
                a[mi][2] = __float_as_uint(p[4]);
                a[mi][3] = __float_as_uint(p[8 * LD + 4]);
            }
#pragma unroll
            for (int ni = 0; ni < 4; ni++) {
                const float* p = &Bs[(wn * 32 + ni * 8 + lq) * LD + kk + lr];
                b[ni][0] = __float_as_uint(p[0]);
                b[ni][1] = __float_as_uint(p[4]);
            }
#pragma unroll
            for (int mi = 0; mi < 4; mi++)
#pragma unroll
                for (int ni = 0; ni < 4; ni++)
                    mma16n8k8(acc[mi][ni], a[mi], b[ni]);
        }
        __syncthreads();
    }

    // epilogue
#pragma unroll
    for (int mi = 0; mi < 4; mi++) {
        const int row0 = bm + wm * 64 + mi * 16 + lq;
#pragma unroll
        for (int ni = 0; ni < 4; ni++) {
            const int col = bn + wn * 32 + ni * 8 + lr * 2;
            float bz0, bz1;
            if (SPLIT) {
                bz0 = col < 64 ? bias1[col] : bias2[col - 64];
                bz1 = (col + 1) < 64 ? bias1[col + 1] : bias2[col + 1 - 64];
            } else {
                bz0 = bias1[col]; bz1 = bias1[col + 1];
            }
            if (row0 < M) {
                float2 o = make_float2(acc[mi][ni][0] + bz0, acc[mi][ni][1] + bz1);
                *reinterpret_cast<float2*>(C + (size_t)row0 * N + col) = o;
            }
            if (row0 + 8 < M) {
                float2 o = make_float2(acc[mi][ni][2] + bz0, acc[mi][ni][3] + bz1);
                *reinterpret_cast<float2*>(C + (size_t)(row0 + 8) * N + col) = o;
            }
        }
    }
}

// ---------------- sampler: scalar phase (per (q,h,p) thread) + gather phase ----------------
__global__ __launch_bounds__(256)
void sample_kernel(const float* __restrict__ refpts) {
    __shared__ int2 s_pc[256 * 4];   // (value_row_idx, attn*bilinear weight) per corner

    const int tid = threadIdx.x;
    const int q0 = blockIdx.x * GQ;
    const int qi = tid >> 5;
    const int h = (tid >> 2) & 7;
    const int p = tid & 3;
    const int q = q0 + qi;

    // ---- scalar phase: one thread per (q,h,p) ----
    const float refx = refpts[q * 2 + 0];
    const float refy = refpts[q * 2 + 1];
    const float* row = g_oa + (size_t)q * 96;
    const float lg = row[64 + h * 4 + p];
    const float ox = row[h * 8 + p * 2 + 0];
    const float oy = row[h * 8 + p * 2 + 1];

    // softmax over p within the quad (lanes p=0..3 share tid>>2)
    float mx = lg;
    mx = fmaxf(mx, __shfl_xor_sync(0xFFFFFFFFu, mx, 1));
    mx = fmaxf(mx, __shfl_xor_sync(0xFFFFFFFFu, mx, 2));
    float e = expf(lg - mx);
    float s = e;
    s += __shfl_xor_sync(0xFFFFFFFFu, s, 1);
    s += __shfl_xor_sync(0xFFFFFFFFu, s, 2);
    const float ap = e / s;

    const float x = (refx + ox * (1.0f / WSP)) * WSP - 0.5f;
    const float y = (refy + oy * (1.0f / HSP)) * HSP - 0.5f;
    const float x0f = floorf(x), y0f = floorf(y);
    const int x0 = (int)x0f, y0 = (int)y0f;
    const float lw = x - x0f, lh = y - y0f;
    const int x1 = x0 + 1, y1 = y0 + 1;

    const float wc[4] = { (1.0f - lh) * (1.0f - lw), (1.0f - lh) * lw,
                          lh * (1.0f - lw),          lh * lw };
    const int xs[4] = { x0, x1, x0, x1 };
    const int ys[4] = { y0, y0, y1, y1 };
#pragma unroll
    for (int c = 0; c < 4; c++) {
        const bool v = (xs[c] >= 0) & (xs[c] < WSP) & (ys[c] >= 0) & (ys[c] < HSP);
        const float w = v ? ap * wc[c] : 0.0f;
        const int idx = v ? (ys[c] * WSP + xs[c]) : 0;
        s_pc[tid * 4 + c] = make_int2(idx, __float_as_int(w));
    }
    __syncthreads();

    // ---- gather phase: warp w handles query q0+w, all 8 heads; lane = channel ----
    const int wid = tid >> 5, lane = tid & 31;
    float* outp = g_sampled + (size_t)(q0 + wid) * DMOD + lane;
#pragma unroll
    for (int hh = 0; hh < NH; hh++) {
        const float* vb = g_value + hh * DH + lane;
        const int base = (wid * 32 + hh * 4) * 4;
        float acc0 = 0.0f, acc1 = 0.0f;
#pragma unroll
        for (int pc = 0; pc < 16; pc += 2) {
            int2 a = s_pc[base + pc];
            int2 b = s_pc[base + pc + 1];
            acc0 += __int_as_float(a.y) * vb[(size_t)a.x * DMOD];
            acc1 += __int_as_float(b.y) * vb[(size_t)b.x * DMOD];
        }
        outp[hh * DH] = acc0 + acc1;
    }
}

// ---------------- launch ----------------
extern "C" void kernel_launch(void* const* d_in, const int* in_sizes, int n_in,
                              void* d_out, int out_size) {
    const float* query  = (const float*)d_in[0];
    const float* qpos   = (const float*)d_in[1];
    const float* refpts = (const float*)d_in[2];
    const float* inp    = (const float*)d_in[3];
    const float* Wv     = (const float*)d_in[4];
    const float* bv     = (const float*)d_in[5];
    const float* Woff   = (const float*)d_in[6];
    const float* boff   = (const float*)d_in[7];
    const float* Wattn  = (const float*)d_in[8];
    const float* battn  = (const float*)d_in[9];
    const float* Wout   = (const float*)d_in[10];
    const float* bout   = (const float*)d_in[11];
    float* out = (float*)d_out;

    float *p_val, *p_oa, *p_samp;
    cudaGetSymbolAddress((void**)&p_val, g_value);
    cudaGetSymbolAddress((void**)&p_oa, g_oa);
    cudaGetSymbolAddress((void**)&p_samp, g_sampled);

    const int gy = (LQ + 127) / 128;  // 313

    // 1. value = input_flatten @ W_value^T + b_value
    mma_gemm<128, false><<<dim3(2, gy), 256>>>(
        inp, nullptr, Wv, nullptr, bv, nullptr, p_val, LQ, DMOD);

    // 2. [off | attn] = (query+query_pos) @ [W_off; W_attn]^T + [b_off; b_attn]
    mma_gemm<96, true><<<dim3(1, gy), 192>>>(
        query, qpos, Woff, Wattn, boff, battn, p_oa, LQ, 96);

    // 3. fused softmax + bilinear sampling
    sample_kernel<<<LQ / GQ, 256>>>(refpts);

    // 4. out = sampled @ W_out^T + b_out
    mma_gemm<128, false><<<dim3(2, gy), 256>>>(
        p_samp, nullptr, Wout, nullptr, bout, nullptr, out, LQ, DMOD);
}

// round 5
// speedup vs baseline: 4.4776x; 1.0550x over previous
#include <cuda_runtime.h>
#include <cstdint>
#include <math.h>

#define LQ   40000
#define DMOD 256
#define NH   8
#define NP   4
#define DH   32
#define HSP  200
#define WSP  200
#define GQ   8

// ---------------- scratch (no allocations allowed) ----------------
__device__ float g_value[LQ * DMOD];
__device__ float g_oa[LQ * 96];
__device__ float g_sampled[LQ * DMOD];

// ---------------- helpers ----------------
__device__ __forceinline__ uint32_t tf32_rna(float x) {
    uint32_t u;
    asm("cvt.rna.tf32.f32 %0, %1;" : "=r"(u) : "f"(x));
    return u;
}
__device__ __forceinline__ void mma16n8k8(float* c, const uint32_t* a, const uint32_t* b) {
    asm volatile(
        "mma.sync.aligned.m16n8k8.row.col.f32.tf32.tf32.f32 "
        "{%0,%1,%2,%3}, {%4,%5,%6,%7}, {%8,%9}, {%0,%1,%2,%3};"
        : "+f"(c[0]), "+f"(c[1]), "+f"(c[2]), "+f"(c[3])
        : "r"(a[0]), "r"(a[1]), "r"(a[2]), "r"(a[3]), "r"(b[0]), "r"(b[1]));
}
__device__ __forceinline__ void cp_async16(uint32_t dst, const void* src) {
    asm volatile("cp.async.cg.shared.global [%0], [%1], 16;" :: "r"(dst), "l"(src));
}
__device__ __forceinline__ void cp_commit() {
    asm volatile("cp.async.commit_group;" ::: "memory");
}
__device__ __forceinline__ void cp_wait2() {
    asm volatile("cp.async.wait_group 2;" ::: "memory");
}

// ============ pipelined tf32 GEMM: C[M,N] = A[M,256] @ B[N,256]^T + bias ============
// 4-stage cp.async pipeline, fp32 in smem, cvt->tf32 after fragment LDS.
template<int BN>
__global__ __launch_bounds__(2 * (BN / 32) * 32, 2)
void pipe_gemm(const float* __restrict__ A, const float* __restrict__ Bw,
               const float* __restrict__ bias, float* __restrict__ C, int M, int N) {
    constexpr int BM = 128;
    constexpr int BK = 32;
    constexpr int LD = 36;
    constexpr int STAGES = 4;
    constexpr int NCHUNK = DMOD / BK;      // 8
    constexpr int NW = 2 * (BN / 32);
    constexpr int NT = NW * 32;
    constexpr int ASZ = BM * LD;           // floats per A stage
    constexpr int BSZ = BN * LD;
    constexpr int SSZ = ASZ + BSZ;
    constexpr int AIT = BM * 8 / NT;       // float4 copies per thread (A)
    constexpr int BIT = BN * 8 / NT;

    extern __shared__ float sm[];
    const uint32_t smem_u32 = (uint32_t)__cvta_generic_to_shared(sm);

    const int tid = threadIdx.x;
    const int wid = tid >> 5;
    const int lane = tid & 31;
    const int wm = wid & 1;
    const int wn = wid >> 1;
    const int bm = blockIdx.y * BM;
    const int bn = blockIdx.x * BN;
    const int lq = lane >> 2;
    const int lr = lane & 3;

    // precompute per-thread copy coordinates
    int arow[AIT], af[AIT];
    const float* asrc[AIT];
#pragma unroll
    for (int i = 0; i < AIT; i++) {
        int idx = tid + i * NT;
        arow[i] = idx >> 3; af[i] = idx & 7;
        int gr = bm + arow[i]; gr = gr < M ? gr : M - 1;
        asrc[i] = A + (size_t)gr * DMOD + af[i] * 4;
    }
    int brow[BIT], bf[BIT];
    const float* bsrc[BIT];
#pragma unroll
    for (int i = 0; i < BIT; i++) {
        int idx = tid + i * NT;
        brow[i] = idx >> 3; bf[i] = idx & 7;
        bsrc[i] = Bw + (size_t)(bn + brow[i]) * DMOD + bf[i] * 4;
    }

    auto issue_stage = [&](int buf, int k0) {
        const uint32_t sb = smem_u32 + (uint32_t)(buf * SSZ) * 4u;
#pragma unroll
        for (int i = 0; i < AIT; i++)
            cp_async16(sb + (uint32_t)(arow[i] * LD + af[i] * 4) * 4u, asrc[i] + k0);
#pragma unroll
        for (int i = 0; i < BIT; i++)
            cp_async16(sb + (uint32_t)(ASZ + brow[i] * LD + bf[i] * 4) * 4u, bsrc[i] + k0);
    };

    float acc[4][4][4];
#pragma unroll
    for (int i = 0; i < 4; i++)
#pragma unroll
        for (int j = 0; j < 4; j++)
#pragma unroll
            for (int r = 0; r < 4; r++) acc[i][j][r] = 0.0f;

    // prologue: fill 3 stages
#pragma unroll
    for (int s = 0; s < STAGES - 1; s++) { issue_stage(s, s * BK); cp_commit(); }

    for (int c = 0; c < NCHUNK; c++) {
        cp_wait2();
        __syncthreads();
        if (c + STAGES - 1 < NCHUNK) issue_stage((c + STAGES - 1) & 3, (c + STAGES - 1) * BK);
        cp_commit();

        const float* As = sm + (c & 3) * SSZ;
        const float* Bs = As + ASZ;
#pragma unroll
        for (int ks = 0; ks < 4; ks++) {
            const int kk = ks * 8;
            uint32_t a[4][4], b[4][2];
#pragma unroll
            for (int mi = 0; mi < 4; mi++) {
                const float* p = &As[(wm * 64 + mi * 16 + lq) * LD + kk + lr];
                a[mi][0] = tf32_rna(p[0]);
                a[mi][1] = tf32_rna(p[8 * LD]);
                a[mi][2] = tf32_rna(p[4]);
                a[mi][3] = tf32_rna(p[8 * LD + 4]);
            }
#pragma unroll
            for (int ni = 0; ni < 4; ni++) {
                const float* p = &Bs[(wn * 32 + ni * 8 + lq) * LD + kk + lr];
                b[ni][0] = tf32_rna(p[0]);
                b[ni][1] = tf32_rna(p[4]);
            }
#pragma unroll
            for (int mi = 0; mi < 4; mi++)
#pragma unroll
                for (int ni = 0; ni < 4; ni++)
                    mma16n8k8(acc[mi][ni], a[mi], b[ni]);
        }
    }

    // epilogue
#pragma unroll
    for (int mi = 0; mi < 4; mi++) {
        const int row0 = bm + wm * 64 + mi * 16 + lq;
#pragma unroll
        for (int ni = 0; ni < 4; ni++) {
            const int col = bn + wn * 32 + ni * 8 + lr * 2;
            const float bz0 = bias[col], bz1 = bias[col + 1];
            if (row0 < M) {
                float2 o = make_float2(acc[mi][ni][0] + bz0, acc[mi][ni][1] + bz1);
                *reinterpret_cast<float2*>(C + (size_t)row0 * N + col) = o;
            }
            if (row0 + 8 < M) {
                float2 o = make_float2(acc[mi][ni][2] + bz0, acc[mi][ni][3] + bz1);
                *reinterpret_cast<float2*>(C + (size_t)(row0 + 8) * N + col) = o;
            }
        }
    }
}

// ============ legacy GEMM for the fused-add split [off|attn] projection ============
__global__ __launch_bounds__(192, 1)
void oa_gemm(const float* __restrict__ A, const float* __restrict__ A2,
             const float* __restrict__ B1, const float* __restrict__ B2,
             const float* __restrict__ bias1, const float* __restrict__ bias2,
             float* __restrict__ C, int M) {
    constexpr int BM = 128, BN = 96, BK = 32, LD = 36;
    constexpr int NT = 192;
    constexpr int AITER = 6;  // ceil(1024/192)
    constexpr int BITER = 4;  // 768/192

    __shared__ float As[BM * LD];
    __shared__ float Bs[BN * LD];

    const int tid = threadIdx.x;
    const int wid = tid >> 5;
    const int lane = tid & 31;
    const int wm = wid & 1;
    const int wn = wid >> 1;
    const int bm = blockIdx.y * BM;
    const int lq = lane >> 2;
    const int lr = lane & 3;

    float acc[4][4][4];
#pragma unroll
    for (int i = 0; i < 4; i++)
#pragma unroll
        for (int j = 0; j < 4; j++)
#pragma unroll
            for (int r = 0; r < 4; r++) acc[i][j][r] = 0.0f;

    float4 ra[AITER], rb[BITER];
    auto load_tiles = [&](int k0) {
#pragma unroll
        for (int i = 0; i < AITER; i++) {
            int idx = tid + i * NT;
            if (idx < BM * 8) {
                int row = idx >> 3, f = idx & 7;
                int gr = bm + row; gr = gr < M ? gr : M - 1;
                float4 v = *reinterpret_cast<const float4*>(A + (size_t)gr * DMOD + k0 + f * 4);
                float4 w = *reinterpret_cast<const float4*>(A2 + (size_t)gr * DMOD + k0 + f * 4);
                v.x += w.x; v.y += w.y; v.z += w.z; v.w += w.w;
                ra[i] = v;
            }
        }
#pragma unroll
        for (int i = 0; i < BITER; i++) {
            int idx = tid + i * NT;
            int row = idx >> 3, f = idx & 7;
            const float* bp = row < 64 ? B1 + (size_t)row * DMOD
                                       : B2 + (size_t)(row - 64) * DMOD;
            rb[i] = *reinterpret_cast<const float4*>(bp + k0 + f * 4);
        }
    };
    auto store_smem = [&]() {
#pragma unroll
        for (int i = 0; i < AITER; i++) {
            int idx = tid + i * NT;
            if (idx < BM * 8) {
                int row = idx >> 3, f = idx & 7;
                uint4 t = make_uint4(tf32_rna(ra[i].x), tf32_rna(ra[i].y),
                                     tf32_rna(ra[i].z), tf32_rna(ra[i].w));
                *reinterpret_cast<uint4*>(&As[row * LD + f * 4]) = t;
            }
        }
#pragma unroll
        for (int i = 0; i < BITER; i++) {
            int idx = tid + i * NT;
            int row = idx >> 3, f = idx & 7;
            uint4 t = make_uint4(tf32_rna(rb[i].x), tf32_rna(rb[i].y),
                                 tf32_rna(rb[i].z), tf32_rna(rb[i].w));
            *reinterpret_cast<uint4*>(&Bs[row * LD + f * 4]) = t;
        }
    };

    load_tiles(0);
    for (int c = 0; c < DMOD / BK; c++) {
        store_smem();
        __syncthreads();
        if (c < DMOD / BK - 1) load_tiles((c + 1) * BK);
#pragma unroll
        for (int ks = 0; ks < 4; ks++) {
            const int kk = ks * 8;
            uint32_t a[4][4], b[4][2];
#pragma unroll
            for (int mi = 0; mi < 4; mi++) {
                const float* p = &As[(wm * 64 + mi * 16 + lq) * LD + kk + lr];
                a[mi][0] = __float_as_uint(p[0]);
                a[mi][1] = __float_as_uint(p[8 * LD]);
                a[mi][2] = __float_as_uint(p[4]);
                a[mi][3] = __float_as_uint(p[8 * LD + 4]);
            }
#pragma unroll
            for (int ni = 0; ni < 4; ni++) {
                const float* p = &Bs[(wn * 32 + ni * 8 + lq) * LD + kk + lr];
                b[ni][0] = __float_as_uint(p[0]);
                b[ni][1] = __float_as_uint(p[4]);
            }
#pragma unroll
            for (int mi = 0; mi < 4; mi++)
#pragma unroll
                for (int ni = 0; ni < 4; ni++)
                    mma16n8k8(acc[mi][ni], a[mi], b[ni]);
        }
        __syncthreads();
    }

#pragma unroll
    for (int mi = 0; mi < 4; mi++) {
        const int row0 = bm + wm * 64 + mi * 16 + lq;
#pragma unroll
        for (int ni = 0; ni < 4; ni++) {
            const int col = wn * 32 + ni * 8 + lr * 2;
            const float bz0 = col < 64 ? bias1[col] : bias2[col - 64];
            const float bz1 = (col + 1) < 64 ? bias1[col + 1] : bias2[col + 1 - 64];
            if (row0 < M) {
                float2 o = make_float2(acc[mi][ni][0] + bz0, acc[mi][ni][1] + bz1);
                *reinterpret_cast<float2*>(C + (size_t)row0 * 96 + col) = o;
            }
            if (row0 + 8 < M) {
                float2 o = make_float2(acc[mi][ni][2] + bz0, acc[mi][ni][3] + bz1);
                *reinterpret_cast<float2*>(C + (size_t)(row0 + 8) * 96 + col) = o;
            }
        }
    }
}

// ---------------- sampler: scalar phase + gather phase ----------------
__global__ __launch_bounds__(256)
void sample_kernel(const float* __restrict__ refpts) {
    __shared__ int2 s_pc[256 * 4];

    const int tid = threadIdx.x;
    const int q0 = blockIdx.x * GQ;
    const int qi = tid >> 5;
    const int h = (tid >> 2) & 7;
    const int p = tid & 3;
    const int q = q0 + qi;

    const float refx = refpts[q * 2 + 0];
    const float refy = refpts[q * 2 + 1];
    const float* row = g_oa + (size_t)q * 96;
    const float lg = row[64 + h * 4 + p];
    const float ox = row[h * 8 + p * 2 + 0];
    const float oy = row[h * 8 + p * 2 + 1];

    float mx = lg;
    mx = fmaxf(mx, __shfl_xor_sync(0xFFFFFFFFu, mx, 1));
    mx = fmaxf(mx, __shfl_xor_sync(0xFFFFFFFFu, mx, 2));
    float e = expf(lg - mx);
    float s = e;
    s += __shfl_xor_sync(0xFFFFFFFFu, s, 1);
    s += __shfl_xor_sync(0xFFFFFFFFu, s, 2);
    const float ap = e / s;

    const float x = (refx + ox * (1.0f / WSP)) * WSP - 0.5f;
    const float y = (refy + oy * (1.0f / HSP)) * HSP - 0.5f;
    const float x0f = floorf(x), y0f = floorf(y);
    const int x0 = (int)x0f, y0 = (int)y0f;
    const float lw = x - x0f, lh = y - y0f;
    const int x1 = x0 + 1, y1 = y0 + 1;

    const float wc[4] = { (1.0f - lh) * (1.0f - lw), (1.0f - lh) * lw,
                          lh * (1.0f - lw),          lh * lw };
    const int xs[4] = { x0, x1, x0, x1 };
    const int ys[4] = { y0, y0, y1, y1 };
#pragma unroll
    for (int c = 0; c < 4; c++) {
        const bool v = (xs[c] >= 0) & (xs[c] < WSP) & (ys[c] >= 0) & (ys[c] < HSP);
        const float w = v ? ap * wc[c] : 0.0f;
        const int idx = v ? (ys[c] * WSP + xs[c]) : 0;
        s_pc[tid * 4 + c] = make_int2(idx, __float_as_int(w));
    }
    __syncthreads();

    const int wid = tid >> 5, lane = tid & 31;
    float* outp = g_sampled + (size_t)(q0 + wid) * DMOD + lane;
#pragma unroll
    for (int hh = 0; hh < NH; hh++) {
        const float* vb = g_value + hh * DH + lane;
        const int base = (wid * 32 + hh * 4) * 4;
        float acc0 = 0.0f, acc1 = 0.0f;
#pragma unroll
        for (int pc = 0; pc < 16; pc += 2) {
            int2 a = s_pc[base + pc];
            int2 b = s_pc[base + pc + 1];
            acc0 += __int_as_float(a.y) * vb[(size_t)a.x * DMOD];
            acc1 += __int_as_float(b.y) * vb[(size_t)b.x * DMOD];
        }
        outp[hh * DH] = acc0 + acc1;
    }
}

// ---------------- launch ----------------
extern "C" void kernel_launch(void* const* d_in, const int* in_sizes, int n_in,
                              void* d_out, int out_size) {
    const float* query  = (const float*)d_in[0];
    const float* qpos   = (const float*)d_in[1];
    const float* refpts = (const float*)d_in[2];
    const float* inp    = (const float*)d_in[3];
    const float* Wv     = (const float*)d_in[4];
    const float* bv     = (const float*)d_in[5];
    const float* Woff   = (const float*)d_in[6];
    const float* boff   = (const float*)d_in[7];
    const float* Wattn  = (const float*)d_in[8];
    const float* battn  = (const float*)d_in[9];
    const float* Wout   = (const float*)d_in[10];
    const float* bout   = (const float*)d_in[11];
    float* out = (float*)d_out;

    float *p_val, *p_oa, *p_samp;
    cudaGetSymbolAddress((void**)&p_val, g_value);
    cudaGetSymbolAddress((void**)&p_oa, g_oa);
    cudaGetSymbolAddress((void**)&p_samp, g_sampled);

    const int gy = (LQ + 127) / 128;  // 313
    const int SMEM_PIPE = 4 * (128 * 36 + 64 * 36) * 4;  // 110592
    cudaFuncSetAttribute(pipe_gemm<64>, cudaFuncAttributeMaxDynamicSharedMemorySize, SMEM_PIPE);

    // 1. value = input_flatten @ W_value^T + b_value
    pipe_gemm<64><<<dim3(4, gy), 128, SMEM_PIPE>>>(inp, Wv, bv, p_val, LQ, DMOD);

    // 2. [off | attn] = (query+query_pos) @ [W_off; W_attn]^T + bias
    oa_gemm<<<dim3(1, gy), 192>>>(query, qpos, Woff, Wattn, boff, battn, p_oa, LQ);

    // 3. fused softmax + bilinear sampling
    sample_kernel<<<LQ / GQ, 256>>>(refpts);

    // 4. out = sampled @ W_out^T + b_out
    pipe_gemm<64><<<dim3(4, gy), 128, SMEM_PIPE>>>(p_samp, Wout, bout, out, LQ, DMOD);
}

// round 6
// speedup vs baseline: 4.5219x; 1.0099x over previous
#include <cuda_runtime.h>
#include <cstdint>
#include <math.h>

#define LQ   40000
#define DMOD 256
#define NH   8
#define NP   4
#define DH   32
#define HSP  200
#define WSP  200
#define GQ   8

// ---------------- scratch (no allocations allowed) ----------------
__device__ float g_value[LQ * DMOD];
__device__ float g_oa[LQ * 96];
__device__ float g_sampled[LQ * DMOD];

// ---------------- helpers ----------------
__device__ __forceinline__ uint32_t tf32_rna(float x) {
    uint32_t u;
    asm("cvt.rna.tf32.f32 %0, %1;" : "=r"(u) : "f"(x));
    return u;
}
__device__ __forceinline__ void mma16n8k8(float* c, const uint32_t* a, const uint32_t* b) {
    asm volatile(
        "mma.sync.aligned.m16n8k8.row.col.f32.tf32.tf32.f32 "
        "{%0,%1,%2,%3}, {%4,%5,%6,%7}, {%8,%9}, {%0,%1,%2,%3};"
        : "+f"(c[0]), "+f"(c[1]), "+f"(c[2]), "+f"(c[3])
        : "r"(a[0]), "r"(a[1]), "r"(a[2]), "r"(a[3]), "r"(b[0]), "r"(b[1]));
}
__device__ __forceinline__ void cp_async16(uint32_t dst, const void* src) {
    asm volatile("cp.async.cg.shared.global [%0], [%1], 16;" :: "r"(dst), "l"(src));
}
__device__ __forceinline__ void cp_commit() {
    asm volatile("cp.async.commit_group;" ::: "memory");
}
__device__ __forceinline__ void cp_wait2() {
    asm volatile("cp.async.wait_group 2;" ::: "memory");
}

// ============ pipelined tf32 GEMM: C[M,N] = A[M,256] @ B[N,256]^T + bias ============
// 256 threads, 8 warps (4 row-groups x 2 col-groups), warp tile 32x32.
// 4-stage cp.async pipeline, fp32 in smem, cvt->tf32 after fragment LDS.
__global__ __launch_bounds__(256, 2)
void pipe_gemm(const float* __restrict__ A, const float* __restrict__ Bw,
               const float* __restrict__ bias, float* __restrict__ C, int M, int N) {
    constexpr int BM = 128;
    constexpr int BN = 64;
    constexpr int BK = 32;
    constexpr int LD = 36;
    constexpr int STAGES = 4;
    constexpr int NCHUNK = DMOD / BK;      // 8
    constexpr int NT = 256;
    constexpr int ASZ = BM * LD;
    constexpr int BSZ = BN * LD;
    constexpr int SSZ = ASZ + BSZ;
    constexpr int AIT = BM * 8 / NT;       // 4
    constexpr int BIT = BN * 8 / NT;       // 2

    extern __shared__ float sm[];
    const uint32_t smem_u32 = (uint32_t)__cvta_generic_to_shared(sm);

    const int tid = threadIdx.x;
    const int wid = tid >> 5;
    const int lane = tid & 31;
    const int wm = wid & 3;                // row group: 32 rows each
    const int wn = wid >> 2;               // col group: 32 cols each
    const int bm = blockIdx.y * BM;
    const int bn = blockIdx.x * BN;
    const int lq = lane >> 2;
    const int lr = lane & 3;

    int arow[AIT], af[AIT];
    const float* asrc[AIT];
#pragma unroll
    for (int i = 0; i < AIT; i++) {
        int idx = tid + i * NT;
        arow[i] = idx >> 3; af[i] = idx & 7;
        int gr = bm + arow[i]; gr = gr < M ? gr : M - 1;
        asrc[i] = A + (size_t)gr * DMOD + af[i] * 4;
    }
    int brow[BIT], bf[BIT];
    const float* bsrc[BIT];
#pragma unroll
    for (int i = 0; i < BIT; i++) {
        int idx = tid + i * NT;
        brow[i] = idx >> 3; bf[i] = idx & 7;
        bsrc[i] = Bw + (size_t)(bn + brow[i]) * DMOD + bf[i] * 4;
    }

    auto issue_stage = [&](int buf, int k0) {
        const uint32_t sb = smem_u32 + (uint32_t)(buf * SSZ) * 4u;
#pragma unroll
        for (int i = 0; i < AIT; i++)
            cp_async16(sb + (uint32_t)(arow[i] * LD + af[i] * 4) * 4u, asrc[i] + k0);
#pragma unroll
        for (int i = 0; i < BIT; i++)
            cp_async16(sb + (uint32_t)(ASZ + brow[i] * LD + bf[i] * 4) * 4u, bsrc[i] + k0);
    };

    float acc[2][4][4];
#pragma unroll
    for (int i = 0; i < 2; i++)
#pragma unroll
        for (int j = 0; j < 4; j++)
#pragma unroll
            for (int r = 0; r < 4; r++) acc[i][j][r] = 0.0f;

#pragma unroll
    for (int s = 0; s < STAGES - 1; s++) { issue_stage(s, s * BK); cp_commit(); }

    for (int c = 0; c < NCHUNK; c++) {
        cp_wait2();
        __syncthreads();
        if (c + STAGES - 1 < NCHUNK) issue_stage((c + STAGES - 1) & 3, (c + STAGES - 1) * BK);
        cp_commit();

        const float* As = sm + (c & 3) * SSZ;
        const float* Bs = As + ASZ;
#pragma unroll
        for (int ks = 0; ks < 4; ks++) {
            const int kk = ks * 8;
            uint32_t a[2][4], b[4][2];
#pragma unroll
            for (int mi = 0; mi < 2; mi++) {
                const float* p = &As[(wm * 32 + mi * 16 + lq) * LD + kk + lr];
                a[mi][0] = tf32_rna(p[0]);
                a[mi][1] = tf32_rna(p[8 * LD]);
                a[mi][2] = tf32_rna(p[4]);
                a[mi][3] = tf32_rna(p[8 * LD + 4]);
            }
#pragma unroll
            for (int ni = 0; ni < 4; ni++) {
                const float* p = &Bs[(wn * 32 + ni * 8 + lq) * LD + kk + lr];
                b[ni][0] = tf32_rna(p[0]);
                b[ni][1] = tf32_rna(p[4]);
            }
#pragma unroll
            for (int mi = 0; mi < 2; mi++)
#pragma unroll
                for (int ni = 0; ni < 4; ni++)
                    mma16n8k8(acc[mi][ni], a[mi], b[ni]);
        }
    }

#pragma unroll
    for (int mi = 0; mi < 2; mi++) {
        const int row0 = bm + wm * 32 + mi * 16 + lq;
#pragma unroll
        for (int ni = 0; ni < 4; ni++) {
            const int col = bn + wn * 32 + ni * 8 + lr * 2;
            const float bz0 = bias[col], bz1 = bias[col + 1];
            if (row0 < M) {
                float2 o = make_float2(acc[mi][ni][0] + bz0, acc[mi][ni][1] + bz1);
                *reinterpret_cast<float2*>(C + (size_t)row0 * N + col) = o;
            }
            if (row0 + 8 < M) {
                float2 o = make_float2(acc[mi][ni][2] + bz0, acc[mi][ni][3] + bz1);
                *reinterpret_cast<float2*>(C + (size_t)(row0 + 8) * N + col) = o;
            }
        }
    }
}

// ============ [off|attn] projection: (query+qpos) @ [W_off; W_attn]^T + bias ============
// 384 threads, 12 warps (4 row x 3 col), warp tile 32x32. Register-prefetch double-issue.
__global__ __launch_bounds__(384, 1)
void oa_gemm(const float* __restrict__ A, const float* __restrict__ A2,
             const float* __restrict__ B1, const float* __restrict__ B2,
             const float* __restrict__ bias1, const float* __restrict__ bias2,
             float* __restrict__ C, int M) {
    constexpr int BM = 128, BN = 96, BK = 32, LD = 36;
    constexpr int NT = 384;
    constexpr int AITER = 3;   // ceil(1024/384)
    constexpr int BITER = 2;   // 768/384

    __shared__ float As[BM * LD];
    __shared__ float Bs[BN * LD];

    const int tid = threadIdx.x;
    const int wid = tid >> 5;
    const int lane = tid & 31;
    const int wm = wid & 3;
    const int wn = wid >> 2;   // 0..2
    const int bm = blockIdx.y * BM;
    const int lq = lane >> 2;
    const int lr = lane & 3;

    float acc[2][4][4];
#pragma unroll
    for (int i = 0; i < 2; i++)
#pragma unroll
        for (int j = 0; j < 4; j++)
#pragma unroll
            for (int r = 0; r < 4; r++) acc[i][j][r] = 0.0f;

    float4 ra[AITER], rb[BITER];
    auto load_tiles = [&](int k0) {
#pragma unroll
        for (int i = 0; i < AITER; i++) {
            int idx = tid + i * NT;
            if (idx < BM * 8) {
                int row = idx >> 3, f = idx & 7;
                int gr = bm + row; gr = gr < M ? gr : M - 1;
                float4 v = *reinterpret_cast<const float4*>(A + (size_t)gr * DMOD + k0 + f * 4);
                float4 w = *reinterpret_cast<const float4*>(A2 + (size_t)gr * DMOD + k0 + f * 4);
                v.x += w.x; v.y += w.y; v.z += w.z; v.w += w.w;
                ra[i] = v;
            }
        }
#pragma unroll
        for (int i = 0; i < BITER; i++) {
            int idx = tid + i * NT;
            int row = idx >> 3, f = idx & 7;
            const float* bp = row < 64 ? B1 + (size_t)row * DMOD
                                       : B2 + (size_t)(row - 64) * DMOD;
            rb[i] = *reinterpret_cast<const float4*>(bp + k0 + f * 4);
        }
    };
    auto store_smem = [&]() {
#pragma unroll
        for (int i = 0; i < AITER; i++) {
            int idx = tid + i * NT;
            if (idx < BM * 8) {
                int row = idx >> 3, f = idx & 7;
                uint4 t = make_uint4(tf32_rna(ra[i].x), tf32_rna(ra[i].y),
                                     tf32_rna(ra[i].z), tf32_rna(ra[i].w));
                *reinterpret_cast<uint4*>(&As[row * LD + f * 4]) = t;
            }
        }
#pragma unroll
        for (int i = 0; i < BITER; i++) {
            int idx = tid + i * NT;
            int row = idx >> 3, f = idx & 7;
            uint4 t = make_uint4(tf32_rna(rb[i].x), tf32_rna(rb[i].y),
                                 tf32_rna(rb[i].z), tf32_rna(rb[i].w));
            *reinterpret_cast<uint4*>(&Bs[row * LD + f * 4]) = t;
        }
    };

    load_tiles(0);
    for (int c = 0; c < DMOD / BK; c++) {
        store_smem();
        __syncthreads();
        if (c < DMOD / BK - 1) load_tiles((c + 1) * BK);
#pragma unroll
        for (int ks = 0; ks < 4; ks++) {
            const int kk = ks * 8;
            uint32_t a[2][4], b[4][2];
#pragma unroll
            for (int mi = 0; mi < 2; mi++) {
                const float* p = &As[(wm * 32 + mi * 16 + lq) * LD + kk + lr];
                a[mi][0] = __float_as_uint(p[0]);
                a[mi][1] = __float_as_uint(p[8 * LD]);
                a[mi][2] = __float_as_uint(p[4]);
                a[mi][3] = __float_as_uint(p[8 * LD + 4]);
            }
#pragma unroll
            for (int ni = 0; ni < 4; ni++) {
                const float* p = &Bs[(wn * 32 + ni * 8 + lq) * LD + kk + lr];
                b[ni][0] = __float_as_uint(p[0]);
                b[ni][1] = __float_as_uint(p[4]);
            }
#pragma unroll
            for (int mi = 0; mi < 2; mi++)
#pragma unroll
                for (int ni = 0; ni < 4; ni++)
                    mma16n8k8(acc[mi][ni], a[mi], b[ni]);
        }
        __syncthreads();
    }

#pragma unroll
    for (int mi = 0; mi < 2; mi++) {
        const int row0 = bm + wm * 32 + mi * 16 + lq;
#pragma unroll
        for (int ni = 0; ni < 4; ni++) {
            const int col = wn * 32 + ni * 8 + lr * 2;
            const float bz0 = col < 64 ? bias1[col] : bias2[col - 64];
            const float bz1 = (col + 1) < 64 ? bias1[col + 1] : bias2[col + 1 - 64];
            if (row0 < M) {
                float2 o = make_float2(acc[mi][ni][0] + bz0, acc[mi][ni][1] + bz1);
                *reinterpret_cast<float2*>(C + (size_t)row0 * 96 + col) = o;
            }
            if (row0 + 8 < M) {
                float2 o = make_float2(acc[mi][ni][2] + bz0, acc[mi][ni][3] + bz1);
                *reinterpret_cast<float2*>(C + (size_t)(row0 + 8) * 96 + col) = o;
            }
        }
    }
}

// ---------------- sampler: scalar phase + gather phase ----------------
__global__ __launch_bounds__(256)
void sample_kernel(const float* __restrict__ refpts) {
    __shared__ int2 s_pc[256 * 4];

    const int tid = threadIdx.x;
    const int q0 = blockIdx.x * GQ;
    const int qi = tid >> 5;
    const int h = (tid >> 2) & 7;
    const int p = tid & 3;
    const int q = q0 + qi;

    const float refx = refpts[q * 2 + 0];
    const float refy = refpts[q * 2 + 1];
    const float* row = g_oa + (size_t)q * 96;
    const float lg = row[64 + h * 4 + p];
    const float ox = row[h * 8 + p * 2 + 0];
    const float oy = row[h * 8 + p * 2 + 1];

    float mx = lg;
    mx = fmaxf(mx, __shfl_xor_sync(0xFFFFFFFFu, mx, 1));
    mx = fmaxf(mx, __shfl_xor_sync(0xFFFFFFFFu, mx, 2));
    float e = expf(lg - mx);
    float s = e;
    s += __shfl_xor_sync(0xFFFFFFFFu, s, 1);
    s += __shfl_xor_sync(0xFFFFFFFFu, s, 2);
    const float ap = e / s;

    const float x = (refx + ox * (1.0f / WSP)) * WSP - 0.5f;
    const float y = (refy + oy * (1.0f / HSP)) * HSP - 0.5f;
    const float x0f = floorf(x), y0f = floorf(y);
    const int x0 = (int)x0f, y0 = (int)y0f;
    const float lw = x - x0f, lh = y - y0f;
    const int x1 = x0 + 1, y1 = y0 + 1;

    const float wc[4] = { (1.0f - lh) * (1.0f - lw), (1.0f - lh) * lw,
                          lh * (1.0f - lw),          lh * lw };
    const int xs[4] = { x0, x1, x0, x1 };
    const int ys[4] = { y0, y0, y1, y1 };
#pragma unroll
    for (int c = 0; c < 4; c++) {
        const bool v = (xs[c] >= 0) & (xs[c] < WSP) & (ys[c] >= 0) & (ys[c] < HSP);
        const float w = v ? ap * wc[c] : 0.0f;
        const int idx = v ? (ys[c] * WSP + xs[c]) : 0;
        s_pc[tid * 4 + c] = make_int2(idx, __float_as_int(w));
    }
    __syncthreads();

    const int wid = tid >> 5, lane = tid & 31;
    float* outp = g_sampled + (size_t)(q0 + wid) * DMOD + lane;
#pragma unroll
    for (int hh = 0; hh < NH; hh++) {
        const float* vb = g_value + hh * DH + lane;
        const int base = (wid * 32 + hh * 4) * 4;
        float acc0 = 0.0f, acc1 = 0.0f;
#pragma unroll
        for (int pc = 0; pc < 16; pc += 2) {
            int2 a = s_pc[base + pc];
            int2 b = s_pc[base + pc + 1];
            acc0 += __int_as_float(a.y) * vb[(size_t)a.x * DMOD];
            acc1 += __int_as_float(b.y) * vb[(size_t)b.x * DMOD];
        }
        outp[hh * DH] = acc0 + acc1;
    }
}

// ---------------- launch ----------------
extern "C" void kernel_launch(void* const* d_in, const int* in_sizes, int n_in,
                              void* d_out, int out_size) {
    const float* query  = (const float*)d_in[0];
    const float* qpos   = (const float*)d_in[1];
    const float* refpts = (const float*)d_in[2];
    const float* inp    = (const float*)d_in[3];
    const float* Wv     = (const float*)d_in[4];
    const float* bv     = (const float*)d_in[5];
    const float* Woff   = (const float*)d_in[6];
    const float* boff   = (const float*)d_in[7];
    const float* Wattn  = (const float*)d_in[8];
    const float* battn  = (const float*)d_in[9];
    const float* Wout   = (const float*)d_in[10];
    const float* bout   = (const float*)d_in[11];
    float* out = (float*)d_out;

    float *p_val, *p_oa, *p_samp;
    cudaGetSymbolAddress((void**)&p_val, g_value);
    cudaGetSymbolAddress((void**)&p_oa, g_oa);
    cudaGetSymbolAddress((void**)&p_samp, g_sampled);

    const int gy = (LQ + 127) / 128;  // 313
    const int SMEM_PIPE = 4 * (128 * 36 + 64 * 36) * 4;  // 110592
    cudaFuncSetAttribute(pipe_gemm, cudaFuncAttributeMaxDynamicSharedMemorySize, SMEM_PIPE);

    // 1. value = input_flatten @ W_value^T + b_value
    pipe_gemm<<<dim3(4, gy), 256, SMEM_PIPE>>>(inp, Wv, bv, p_val, LQ, DMOD);

    // 2. [off | attn] = (query+query_pos) @ [W_off; W_attn]^T + bias
    oa_gemm<<<dim3(1, gy), 384>>>(query, qpos, Woff, Wattn, boff, battn, p_oa, LQ);

    // 3. fused softmax + bilinear sampling
    sample_kernel<<<LQ / GQ, 256>>>(refpts);

    // 4. out = sampled @ W_out^T + b_out
    pipe_gemm<<<dim3(4, gy), 256, SMEM_PIPE>>>(p_samp, Wout, bout, out, LQ, DMOD);
}

// round 7
// speedup vs baseline: 4.6326x; 1.0245x over previous
#include <cuda_runtime.h>
#include <cstdint>
#include <math.h>

#define LQ   40000
#define DMOD 256
#define NH   8
#define NP   4
#define DH   32
#define HSP  200
#define WSP  200
#define GQ   8

// ---------------- scratch (no allocations allowed) ----------------
__device__ float g_value[LQ * DMOD];
__device__ float g_oa[LQ * 96];
__device__ float g_sampled[LQ * DMOD];   // stored pre-rounded to tf32
__device__ float g_inp[LQ * DMOD];       // tf32-rounded input_flatten
__device__ float g_wv[DMOD * DMOD];      // tf32-rounded W_value
__device__ float g_wout[DMOD * DMOD];    // tf32-rounded W_out

// ---------------- helpers ----------------
__device__ __forceinline__ uint32_t tf32_rna(float x) {
    uint32_t u;
    asm("cvt.rna.tf32.f32 %0, %1;" : "=r"(u) : "f"(x));
    return u;
}
__device__ __forceinline__ void mma16n8k8(float* c, const uint32_t* a, const uint32_t* b) {
    asm volatile(
        "mma.sync.aligned.m16n8k8.row.col.f32.tf32.tf32.f32 "
        "{%0,%1,%2,%3}, {%4,%5,%6,%7}, {%8,%9}, {%0,%1,%2,%3};"
        : "+f"(c[0]), "+f"(c[1]), "+f"(c[2]), "+f"(c[3])
        : "r"(a[0]), "r"(a[1]), "r"(a[2]), "r"(a[3]), "r"(b[0]), "r"(b[1]));
}
__device__ __forceinline__ void ldsm4(uint32_t& r0, uint32_t& r1, uint32_t& r2,
                                      uint32_t& r3, uint32_t addr) {
    asm volatile("ldmatrix.sync.aligned.m8n8.x4.shared.b16 {%0,%1,%2,%3}, [%4];"
                 : "=r"(r0), "=r"(r1), "=r"(r2), "=r"(r3) : "r"(addr));
}
__device__ __forceinline__ void cp_async16(uint32_t dst, const void* src) {
    asm volatile("cp.async.cg.shared.global [%0], [%1], 16;" :: "r"(dst), "l"(src));
}
__device__ __forceinline__ void cp_commit() {
    asm volatile("cp.async.commit_group;" ::: "memory");
}
__device__ __forceinline__ void cp_wait2() {
    asm volatile("cp.async.wait_group 2;" ::: "memory");
}

// ---------------- tf32 rounding pass ----------------
__global__ void round_tf32(const float4* __restrict__ src, uint4* __restrict__ dst, int n4) {
    int i = blockIdx.x * blockDim.x + threadIdx.x;
    if (i < n4) {
        float4 v = src[i];
        dst[i] = make_uint4(tf32_rna(v.x), tf32_rna(v.y), tf32_rna(v.z), tf32_rna(v.w));
    }
}

// ============ pipelined tf32 GEMM: C[M,N] = A[M,256] @ B[N,256]^T + bias ============
// Inputs PRE-ROUNDED to tf32. 256 threads, 8 warps (4x2), warp tile 32x32.
// 4-stage cp.async; fragments via ldmatrix.x4 (no cvt in inner loop).
__global__ __launch_bounds__(256, 2)
void pipe_gemm(const float* __restrict__ A, const float* __restrict__ Bw,
               const float* __restrict__ bias, float* __restrict__ C, int M, int N) {
    constexpr int BM = 128;
    constexpr int BN = 64;
    constexpr int BK = 32;
    constexpr int LD = 36;
    constexpr int STAGES = 4;
    constexpr int NCHUNK = DMOD / BK;
    constexpr int NT = 256;
    constexpr int ASZ = BM * LD;
    constexpr int BSZ = BN * LD;
    constexpr int SSZ = ASZ + BSZ;
    constexpr int AIT = BM * 8 / NT;   // 4
    constexpr int BIT = BN * 8 / NT;   // 2

    extern __shared__ float sm[];
    const uint32_t smem_u32 = (uint32_t)__cvta_generic_to_shared(sm);

    const int tid = threadIdx.x;
    const int wid = tid >> 5;
    const int lane = tid & 31;
    const int wm = wid & 3;
    const int wn = wid >> 2;
    const int bm = blockIdx.y * BM;
    const int bn = blockIdx.x * BN;
    const int lq = lane >> 2;
    const int lr = lane & 3;

    // ldmatrix lane->address offsets
    const int arow_l = wm * 32 + (lane & 15);
    const int acol_l = (lane >> 4) << 2;
    const int brow_l = wn * 32 + (lane & 7) + ((lane >> 4) << 3);
    const int bcol_l = ((lane >> 3) & 1) << 2;

    int arow[AIT], af[AIT];
    const float* asrc[AIT];
#pragma unroll
    for (int i = 0; i < AIT; i++) {
        int idx = tid + i * NT;
        arow[i] = idx >> 3; af[i] = idx & 7;
        int gr = bm + arow[i]; gr = gr < M ? gr : M - 1;
        asrc[i] = A + (size_t)gr * DMOD + af[i] * 4;
    }
    int brow[BIT], bf[BIT];
    const float* bsrc[BIT];
#pragma unroll
    for (int i = 0; i < BIT; i++) {
        int idx = tid + i * NT;
        brow[i] = idx >> 3; bf[i] = idx & 7;
        bsrc[i] = Bw + (size_t)(bn + brow[i]) * DMOD + bf[i] * 4;
    }

    auto issue_stage = [&](int buf, int k0) {
        const uint32_t sb = smem_u32 + (uint32_t)(buf * SSZ) * 4u;
#pragma unroll
        for (int i = 0; i < AIT; i++)
            cp_async16(sb + (uint32_t)(arow[i] * LD + af[i] * 4) * 4u, asrc[i] + k0);
#pragma unroll
        for (int i = 0; i < BIT; i++)
            cp_async16(sb + (uint32_t)(ASZ + brow[i] * LD + bf[i] * 4) * 4u, bsrc[i] + k0);
    };

    float acc[2][4][4];
#pragma unroll
    for (int i = 0; i < 2; i++)
#pragma unroll
        for (int j = 0; j < 4; j++)
#pragma unroll
            for (int r = 0; r < 4; r++) acc[i][j][r] = 0.0f;

#pragma unroll
    for (int s = 0; s < STAGES - 1; s++) { issue_stage(s, s * BK); cp_commit(); }

    for (int c = 0; c < NCHUNK; c++) {
        cp_wait2();
        __syncthreads();
        if (c + STAGES - 1 < NCHUNK) issue_stage((c + STAGES - 1) & 3, (c + STAGES - 1) * BK);
        cp_commit();

        const uint32_t As_u = smem_u32 + (uint32_t)((c & 3) * SSZ) * 4u;
        const uint32_t Bs_u = As_u + (uint32_t)ASZ * 4u;
#pragma unroll
        for (int ks = 0; ks < 4; ks++) {
            const int kk = ks * 8;
            uint32_t a[2][4], bA[4], bB[4];
#pragma unroll
            for (int mi = 0; mi < 2; mi++)
                ldsm4(a[mi][0], a[mi][1], a[mi][2], a[mi][3],
                      As_u + (uint32_t)((arow_l + mi * 16) * LD + kk + acol_l) * 4u);
            ldsm4(bA[0], bA[1], bA[2], bA[3],
                  Bs_u + (uint32_t)(brow_l * LD + kk + bcol_l) * 4u);
            ldsm4(bB[0], bB[1], bB[2], bB[3],
                  Bs_u + (uint32_t)((brow_l + 16) * LD + kk + bcol_l) * 4u);
#pragma unroll
            for (int mi = 0; mi < 2; mi++) {
                mma16n8k8(acc[mi][0], a[mi], &bA[0]);
                mma16n8k8(acc[mi][1], a[mi], &bA[2]);
                mma16n8k8(acc[mi][2], a[mi], &bB[0]);
                mma16n8k8(acc[mi][3], a[mi], &bB[2]);
            }
        }
    }

#pragma unroll
    for (int mi = 0; mi < 2; mi++) {
        const int row0 = bm + wm * 32 + mi * 16 + lq;
#pragma unroll
        for (int ni = 0; ni < 4; ni++) {
            const int col = bn + wn * 32 + ni * 8 + lr * 2;
            const float bz0 = bias[col], bz1 = bias[col + 1];
            if (row0 < M) {
                float2 o = make_float2(acc[mi][ni][0] + bz0, acc[mi][ni][1] + bz1);
                *reinterpret_cast<float2*>(C + (size_t)row0 * N + col) = o;
            }
            if (row0 + 8 < M) {
                float2 o = make_float2(acc[mi][ni][2] + bz0, acc[mi][ni][3] + bz1);
                *reinterpret_cast<float2*>(C + (size_t)(row0 + 8) * N + col) = o;
            }
        }
    }
}

// ============ [off|attn] projection: (query+qpos) @ [W_off; W_attn]^T + bias ============
__global__ __launch_bounds__(384, 1)
void oa_gemm(const float* __restrict__ A, const float* __restrict__ A2,
             const float* __restrict__ B1, const float* __restrict__ B2,
             const float* __restrict__ bias1, const float* __restrict__ bias2,
             float* __restrict__ C, int M) {
    constexpr int BM = 128, BN = 96, BK = 32, LD = 36;
    constexpr int NT = 384;
    constexpr int AITER = 3;
    constexpr int BITER = 2;

    __shared__ float As[BM * LD];
    __shared__ float Bs[BN * LD];

    const int tid = threadIdx.x;
    const int wid = tid >> 5;
    const int lane = tid & 31;
    const int wm = wid & 3;
    const int wn = wid >> 2;
    const int bm = blockIdx.y * BM;
    const int lq = lane >> 2;
    const int lr = lane & 3;

    const int arow_l = wm * 32 + (lane & 15);
    const int acol_l = (lane >> 4) << 2;
    const int brow_l = wn * 32 + (lane & 7) + ((lane >> 4) << 3);
    const int bcol_l = ((lane >> 3) & 1) << 2;
    const uint32_t As_u = (uint32_t)__cvta_generic_to_shared(As);
    const uint32_t Bs_u = (uint32_t)__cvta_generic_to_shared(Bs);

    float acc[2][4][4];
#pragma unroll
    for (int i = 0; i < 2; i++)
#pragma unroll
        for (int j = 0; j < 4; j++)
#pragma unroll
            for (int r = 0; r < 4; r++) acc[i][j][r] = 0.0f;

    float4 ra[AITER], rb[BITER];
    auto load_tiles = [&](int k0) {
#pragma unroll
        for (int i = 0; i < AITER; i++) {
            int idx = tid + i * NT;
            if (idx < BM * 8) {
                int row = idx >> 3, f = idx & 7;
                int gr = bm + row; gr = gr < M ? gr : M - 1;
                float4 v = *reinterpret_cast<const float4*>(A + (size_t)gr * DMOD + k0 + f * 4);
                float4 w = *reinterpret_cast<const float4*>(A2 + (size_t)gr * DMOD + k0 + f * 4);
                v.x += w.x; v.y += w.y; v.z += w.z; v.w += w.w;
                ra[i] = v;
            }
        }
#pragma unroll
        for (int i = 0; i < BITER; i++) {
            int idx = tid + i * NT;
            int row = idx >> 3, f = idx & 7;
            const float* bp = row < 64 ? B1 + (size_t)row * DMOD
                                       : B2 + (size_t)(row - 64) * DMOD;
            rb[i] = *reinterpret_cast<const float4*>(bp + k0 + f * 4);
        }
    };
    auto store_smem = [&]() {
#pragma unroll
        for (int i = 0; i < AITER; i++) {
            int idx = tid + i * NT;
            if (idx < BM * 8) {
                int row = idx >> 3, f = idx & 7;
                uint4 t = make_uint4(tf32_rna(ra[i].x), tf32_rna(ra[i].y),
                                     tf32_rna(ra[i].z), tf32_rna(ra[i].w));
                *reinterpret_cast<uint4*>(&As[row * LD + f * 4]) = t;
            }
        }
#pragma unroll
        for (int i = 0; i < BITER; i++) {
            int idx = tid + i * NT;
            int row = idx >> 3, f = idx & 7;
            uint4 t = make_uint4(tf32_rna(rb[i].x), tf32_rna(rb[i].y),
                                 tf32_rna(rb[i].z), tf32_rna(rb[i].w));
            *reinterpret_cast<uint4*>(&Bs[row * LD + f * 4]) = t;
        }
    };

    load_tiles(0);
    for (int c = 0; c < DMOD / BK; c++) {
        store_smem();
        __syncthreads();
        if (c < DMOD / BK - 1) load_tiles((c + 1) * BK);
#pragma unroll
        for (int ks = 0; ks < 4; ks++) {
            const int kk = ks * 8;
            uint32_t a[2][4], bA[4], bB[4];
#pragma unroll
            for (int mi = 0; mi < 2; mi++)
                ldsm4(a[mi][0], a[mi][1], a[mi][2], a[mi][3],
                      As_u + (uint32_t)((arow_l + mi * 16) * LD + kk + acol_l) * 4u);
            ldsm4(bA[0], bA[1], bA[2], bA[3],
                  Bs_u + (uint32_t)(brow_l * LD + kk + bcol_l) * 4u);
            ldsm4(bB[0], bB[1], bB[2], bB[3],
                  Bs_u + (uint32_t)((brow_l + 16) * LD + kk + bcol_l) * 4u);
#pragma unroll
            for (int mi = 0; mi < 2; mi++) {
                mma16n8k8(acc[mi][0], a[mi], &bA[0]);
                mma16n8k8(acc[mi][1], a[mi], &bA[2]);
                mma16n8k8(acc[mi][2], a[mi], &bB[0]);
                mma16n8k8(acc[mi][3], a[mi], &bB[2]);
            }
        }
        __syncthreads();
    }

#pragma unroll
    for (int mi = 0; mi < 2; mi++) {
        const int row0 = bm + wm * 32 + mi * 16 + lq;
#pragma unroll
        for (int ni = 0; ni < 4; ni++) {
            const int col = wn * 32 + ni * 8 + lr * 2;
            const float bz0 = col < 64 ? bias1[col] : bias2[col - 64];
            const float bz1 = (col + 1) < 64 ? bias1[col + 1] : bias2[col + 1 - 64];
            if (row0 < M) {
                float2 o = make_float2(acc[mi][ni][0] + bz0, acc[mi][ni][1] + bz1);
                *reinterpret_cast<float2*>(C + (size_t)row0 * 96 + col) = o;
            }
            if (row0 + 8 < M) {
                float2 o = make_float2(acc[mi][ni][2] + bz0, acc[mi][ni][3] + bz1);
                *reinterpret_cast<float2*>(C + (size_t)(row0 + 8) * 96 + col) = o;
            }
        }
    }
}

// ---------------- sampler: scalar phase + gather phase ----------------
__global__ __launch_bounds__(256)
void sample_kernel(const float* __restrict__ refpts) {
    __shared__ int2 s_pc[256 * 4];

    const int tid = threadIdx.x;
    const int q0 = blockIdx.x * GQ;
    const int qi = tid >> 5;
    const int h = (tid >> 2) & 7;
    const int p = tid & 3;
    const int q = q0 + qi;

    const float refx = refpts[q * 2 + 0];
    const float refy = refpts[q * 2 + 1];
    const float* row = g_oa + (size_t)q * 96;
    const float lg = row[64 + h * 4 + p];
    const float ox = row[h * 8 + p * 2 + 0];
    const float oy = row[h * 8 + p * 2 + 1];

    float mx = lg;
    mx = fmaxf(mx, __shfl_xor_sync(0xFFFFFFFFu, mx, 1));
    mx = fmaxf(mx, __shfl_xor_sync(0xFFFFFFFFu, mx, 2));
    float e = expf(lg - mx);
    float s = e;
    s += __shfl_xor_sync(0xFFFFFFFFu, s, 1);
    s += __shfl_xor_sync(0xFFFFFFFFu, s, 2);
    const float ap = e / s;

    const float x = (refx + ox * (1.0f / WSP)) * WSP - 0.5f;
    const float y = (refy + oy * (1.0f / HSP)) * HSP - 0.5f;
    const float x0f = floorf(x), y0f = floorf(y);
    const int x0 = (int)x0f, y0 = (int)y0f;
    const float lw = x - x0f, lh = y - y0f;
    const int x1 = x0 + 1, y1 = y0 + 1;

    const float wc[4] = { (1.0f - lh) * (1.0f - lw), (1.0f - lh) * lw,
                          lh * (1.0f - lw),          lh * lw };
    const int xs[4] = { x0, x1, x0, x1 };
    const int ys[4] = { y0, y0, y1, y1 };
#pragma unroll
    for (int c = 0; c < 4; c++) {
        const bool v = (xs[c] >= 0) & (xs[c] < WSP) & (ys[c] >= 0) & (ys[c] < HSP);
        const float w = v ? ap * wc[c] : 0.0f;
        const int idx = v ? (ys[c] * WSP + xs[c]) : 0;
        s_pc[tid * 4 + c] = make_int2(idx, __float_as_int(w));
    }
    __syncthreads();

    const int wid = tid >> 5, lane = tid & 31;
    float* outp = g_sampled + (size_t)(q0 + wid) * DMOD + lane;
#pragma unroll
    for (int hh = 0; hh < NH; hh++) {
        const float* vb = g_value + hh * DH + lane;
        const int base = (wid * 32 + hh * 4) * 4;
        float acc0 = 0.0f, acc1 = 0.0f;
#pragma unroll
        for (int pc = 0; pc < 16; pc += 2) {
            int2 a = s_pc[base + pc];
            int2 b = s_pc[base + pc + 1];
            acc0 += __int_as_float(a.y) * vb[(size_t)a.x * DMOD];
            acc1 += __int_as_float(b.y) * vb[(size_t)b.x * DMOD];
        }
        // store pre-rounded to tf32 so the output GEMM needs no cvt
        outp[hh * DH] = __uint_as_float(tf32_rna(acc0 + acc1));
    }
}

// ---------------- launch ----------------
extern "C" void kernel_launch(void* const* d_in, const int* in_sizes, int n_in,
                              void* d_out, int out_size) {
    const float* query  = (const float*)d_in[0];
    const float* qpos   = (const float*)d_in[1];
    const float* refpts = (const float*)d_in[2];
    const float* inp    = (const float*)d_in[3];
    const float* Wv     = (const float*)d_in[4];
    const float* bv     = (const float*)d_in[5];
    const float* Woff   = (const float*)d_in[6];
    const float* boff   = (const float*)d_in[7];
    const float* Wattn  = (const float*)d_in[8];
    const float* battn  = (const float*)d_in[9];
    const float* Wout   = (const float*)d_in[10];
    const float* bout   = (const float*)d_in[11];
    float* out = (float*)d_out;

    float *p_val, *p_oa, *p_samp, *p_inp, *p_wv, *p_wout;
    cudaGetSymbolAddress((void**)&p_val, g_value);
    cudaGetSymbolAddress((void**)&p_oa, g_oa);
    cudaGetSymbolAddress((void**)&p_samp, g_sampled);
    cudaGetSymbolAddress((void**)&p_inp, g_inp);
    cudaGetSymbolAddress((void**)&p_wv, g_wv);
    cudaGetSymbolAddress((void**)&p_wout, g_wout);

    const int gy = (LQ + 127) / 128;  // 313
    const int SMEM_PIPE = 4 * (128 * 36 + 64 * 36) * 4;  // 110592
    cudaFuncSetAttribute(pipe_gemm, cudaFuncAttributeMaxDynamicSharedMemorySize, SMEM_PIPE);

    // 0. tf32-round GEMM operands once
    {
        int n4 = LQ * DMOD / 4;
        round_tf32<<<(n4 + 255) / 256, 256>>>((const float4*)inp, (uint4*)p_inp, n4);
        int w4 = DMOD * DMOD / 4;
        round_tf32<<<(w4 + 255) / 256, 256>>>((const float4*)Wv, (uint4*)p_wv, w4);
        round_tf32<<<(w4 + 255) / 256, 256>>>((const float4*)Wout, (uint4*)p_wout, w4);
    }

    // 1. value = input_flatten @ W_value^T + b_value
    pipe_gemm<<<dim3(4, gy), 256, SMEM_PIPE>>>(p_inp, p_wv, bv, p_val, LQ, DMOD);

    // 2. [off | attn] = (query+query_pos) @ [W_off; W_attn]^T + bias
    oa_gemm<<<dim3(1, gy), 384>>>(query, qpos, Woff, Wattn, boff, battn, p_oa, LQ);

    // 3. fused softmax + bilinear sampling (stores tf32-rounded)
    sample_kernel<<<LQ / GQ, 256>>>(refpts);

    // 4. out = sampled @ W_out^T + b_out
    pipe_gemm<<<dim3(4, gy), 256, SMEM_PIPE>>>(p_samp, p_wout, bout, out, LQ, DMOD);
}